// round 2
// baseline (speedup 1.0000x reference)
#include <cuda_runtime.h>
#include <cstdint>

#define BATCH   16
#define NANCH   25200
#define NCH     85
#define NCLS    80
#define TOPK    1024
#define MAXDET  300
#define CONF_THR 0.6f
#define IOU_THR  0.45f
#define OFFS     4096.0f
#define NBINS    4096

// ---------------- static device scratch (no allocations allowed) ----------------
__device__ float         g_score[BATCH * NANCH];
__device__ unsigned char g_cls[BATCH * NANCH];
__device__ int           g_topk_idx[BATCH * TOPK];
__device__ float         g_topk_score[BATCH * TOPK];
__device__ float4        g_nmsbox[BATCH * TOPK];
__device__ unsigned int  g_mask[BATCH * TOPK * 32];

// ---------------- K1: per-anchor score / class (warp per anchor) ----------------
__global__ void k_score(const float* __restrict__ pred) {
    int gwarp = (blockIdx.x * blockDim.x + threadIdx.x) >> 5;
    int lane  = threadIdx.x & 31;
    if (gwarp >= BATCH * NANCH) return;
    const float* base = pred + (size_t)gwarp * NCH;
    float obj = base[4];
    // products first (matches reference: cls_scores = pred[5:] * obj, then max/argmax)
    float best = -2.0f; int bidx = 0;
    #pragma unroll
    for (int r = 0; r < 3; r++) {
        int j = lane + 32 * r;
        if (j < NCLS) {
            float p = __fmul_rn(obj, base[5 + j]);
            if (p > best) { best = p; bidx = j; }   // strict > keeps lower index on tie
        }
    }
    #pragma unroll
    for (int off = 16; off > 0; off >>= 1) {
        float ob = __shfl_down_sync(0xffffffffu, best, off);
        int   oi = __shfl_down_sync(0xffffffffu, bidx, off);
        if (ob > best || (ob == best && oi < bidx)) { best = ob; bidx = oi; }
    }
    if (lane == 0) {
        bool valid = (obj > CONF_THR) && (best > CONF_THR);
        g_score[gwarp] = valid ? best : -1.0f;
        g_cls[gwarp]   = (unsigned char)bidx;
    }
}

// ---------------- K2: per-image exact top-1024 via histogram + bitonic sort -----
__global__ void k_select(const float* __restrict__ pred) {
    int b   = blockIdx.x;
    int tid = threadIdx.x;                 // 1024 threads
    __shared__ int hist[NBINS];
    __shared__ unsigned long long sbuf[2 * TOPK];
    __shared__ int partial[1024];
    __shared__ int sup[32];
    __shared__ int sh_T;
    __shared__ int counter;

    for (int i = tid; i < NBINS; i += 1024) hist[i] = 0;
    if (tid == 0) counter = 0;
    __syncthreads();

    const float* sc = g_score + (size_t)b * NANCH;
    const float kBinScale = (float)NBINS / 0.4f;

    for (int i = tid; i < NANCH; i += 1024) {
        float s = sc[i];
        if (s > CONF_THR) {
            int bin = (int)((s - CONF_THR) * kBinScale);
            bin = min(max(bin, 0), NBINS - 1);
            atomicAdd(&hist[bin], 1);
        }
    }
    __syncthreads();

    int ps = 0;
    #pragma unroll
    for (int k = 0; k < 4; k++) ps += hist[4 * tid + k];
    partial[tid] = ps;
    __syncthreads();

    if (tid < 32) {
        int s = 0;
        for (int g = 0; g < 32; g++) s += partial[32 * tid + g];
        sup[tid] = s;
        __syncwarp();
        if (tid == 0) {
            int acc = 0, T = 0, l;
            for (l = 31; l >= 0; l--) { if (acc + sup[l] >= TOPK) break; acc += sup[l]; }
            if (l >= 0) {
                int g;
                for (g = 31; g >= 0; g--) { int v = partial[32 * l + g]; if (acc + v >= TOPK) break; acc += v; }
                if (g < 0) g = 0;
                int bb;
                for (bb = 3; bb >= 0; bb--) { int v = hist[4 * (32 * l + g) + bb]; if (acc + v >= TOPK) break; acc += v; }
                if (bb < 0) bb = 0;
                T = 4 * (32 * l + g) + bb;
            }
            sh_T = T;
        }
    }
    __syncthreads();
    int T = sh_T;

    for (int i = tid; i < NANCH; i += 1024) {
        float s = sc[i];
        if (s > CONF_THR) {
            int bin = (int)((s - CONF_THR) * kBinScale);
            bin = min(max(bin, 0), NBINS - 1);
            if (bin >= T) {
                int pos = atomicAdd(&counter, 1);
                if (pos < 2 * TOPK) {
                    unsigned int u = __float_as_uint(s) ^ 0x80000000u;  // positive float -> order-preserving
                    sbuf[pos] = (((unsigned long long)(~u)) << 32) | (unsigned int)i;
                }
            }
        }
    }
    __syncthreads();
    int M = min(counter, 2 * TOPK);
    for (int i = tid; i < 2 * TOPK; i += 1024)
        if (i >= M) sbuf[i] = 0xFFFFFFFFFFFFFFFFull;
    __syncthreads();

    // bitonic sort ascending: primary ~score_bits (=> score descending), ties idx ascending
    for (int k = 2; k <= 2 * TOPK; k <<= 1) {
        for (int j = k >> 1; j > 0; j >>= 1) {
            for (int e = tid; e < 2 * TOPK; e += 1024) {
                int partner = e ^ j;
                if (partner > e) {
                    bool asc = ((e & k) == 0);
                    unsigned long long a = sbuf[e], c = sbuf[partner];
                    if ((a > c) == asc) { sbuf[e] = c; sbuf[partner] = a; }
                }
            }
            __syncthreads();
        }
    }

    // emit top-1024: idx, score, class-offset nms box
    if (tid < TOPK) {
        int slot = b * TOPK + tid;
        if (tid < M) {
            unsigned long long key = sbuf[tid];
            int idx = (int)(key & 0xFFFFFFFFu);
            unsigned int u = ~((unsigned int)(key >> 32));
            float s = __uint_as_float(u ^ 0x80000000u);
            g_topk_score[slot] = s;
            g_topk_idx[slot]   = idx;
            const float* p = pred + ((size_t)b * NANCH + idx) * NCH;
            float cx = p[0], cy = p[1], w = p[2], h = p[3];
            float hw = __fmul_rn(w, 0.5f), hh = __fmul_rn(h, 0.5f);
            float x1 = __fsub_rn(cx, hw), y1 = __fsub_rn(cy, hh);
            float x2 = __fadd_rn(cx, hw), y2 = __fadd_rn(cy, hh);
            float off = __fmul_rn((float)g_cls[(size_t)b * NANCH + idx], OFFS);
            g_nmsbox[slot] = make_float4(__fadd_rn(x1, off), __fadd_rn(y1, off),
                                         __fadd_rn(x2, off), __fadd_rn(y2, off));
        } else {
            g_topk_score[slot] = -1.0f;
            g_topk_idx[slot]   = 0;
            float far = -1.0e9f - (float)tid * 16.0f;   // inert: never kept, never suppresses
            g_nmsbox[slot] = make_float4(far, far, far + 1.0f, far + 1.0f);
        }
    }
}

// ---------------- K3: suppression bitmask, iou computed exactly per reference ---
__global__ void k_mask() {
    int b = blockIdx.x, q = blockIdx.y;     // q in [0,4): column quarter
    int i = threadIdx.x;                    // 1024 threads, one row each
    __shared__ float4 boxes[TOPK];
    for (int t = threadIdx.x; t < TOPK; t += 1024) boxes[t] = g_nmsbox[b * TOPK + t];
    __syncthreads();

    float4 bi = boxes[i];
    float area_i = __fmul_rn(__fsub_rn(bi.z, bi.x), __fsub_rn(bi.w, bi.y));
    int j0 = q * 256;
    #pragma unroll
    for (int w = 0; w < 8; w++) {
        unsigned int m = 0;
        #pragma unroll 4
        for (int t = 0; t < 32; t++) {
            int j = j0 + w * 32 + t;
            if (j > i) {
                float4 bj = boxes[j];
                float area_j = __fmul_rn(__fsub_rn(bj.z, bj.x), __fsub_rn(bj.w, bj.y));
                float ltx = fmaxf(bi.x, bj.x), lty = fmaxf(bi.y, bj.y);
                float rbx = fminf(bi.z, bj.z), rby = fminf(bi.w, bj.w);
                float wx = fmaxf(__fsub_rn(rbx, ltx), 0.0f);
                float wy = fmaxf(__fsub_rn(rby, lty), 0.0f);
                float inter = __fmul_rn(wx, wy);
                float denom = __fadd_rn(__fsub_rn(__fadd_rn(area_i, area_j), inter), 1e-9f);
                float iou = inter / denom;
                if (iou > IOU_THR) m |= (1u << t);
            }
        }
        g_mask[((size_t)b * TOPK + i) * 32 + q * 8 + w] = m;
    }
}

// ---------------- K4: serial greedy walk (1 warp) + parallel output emit --------
__global__ void k_out(const float* __restrict__ pred,
                      const float* __restrict__ logits,
                      float* __restrict__ out) {
    int b   = blockIdx.x;
    int tid = threadIdx.x;                  // 1024 threads
    __shared__ int sel[MAXDET];
    __shared__ int sh_count;

    if (tid < 32) {
        unsigned int removed = 0;           // lane L owns suppression bits for j in [32L, 32L+32)
        int count = 0;
        const float* scores = g_topk_score + (size_t)b * TOPK;
        const unsigned int* mask = g_mask + (size_t)b * TOPK * 32;
        for (int i = 0; i < TOPK && count < MAXDET; i++) {
            float s = scores[i];
            if (s <= CONF_THR) break;       // sorted descending: rest invalid
            unsigned int rw = __shfl_sync(0xffffffffu, removed, i >> 5);
            bool sup = (rw >> (i & 31)) & 1u;
            if (!sup) {
                removed |= mask[(size_t)i * 32 + tid];
                if (tid == 0) sel[count] = i;
                count++;
            }
        }
        if (tid == 0) sh_count = count;
    }
    __syncthreads();
    int count = sh_count;

    float* det  = out;                                      // [B,300,6]
    float* vout = out + BATCH * MAXDET * 6;                 // [B,300]
    float* lout = vout + BATCH * MAXDET;                    // [B,300,80]

    for (int s = tid; s < MAXDET; s += 1024) {
        float d0 = 0, d1 = 0, d2 = 0, d3 = 0, d4 = 0, d5 = 0, v = 0;
        if (s < count) {
            int i   = sel[s];
            int idx = g_topk_idx[b * TOPK + i];
            const float* p = pred + ((size_t)b * NANCH + idx) * NCH;
            float cx = p[0], cy = p[1], w = p[2], h = p[3];
            float hw = __fmul_rn(w, 0.5f), hh = __fmul_rn(h, 0.5f);
            d0 = __fsub_rn(cx, hw); d1 = __fsub_rn(cy, hh);
            d2 = __fadd_rn(cx, hw); d3 = __fadd_rn(cy, hh);
            d4 = g_topk_score[b * TOPK + i];
            d5 = (float)g_cls[(size_t)b * NANCH + idx];
            v = 1.0f;
        }
        float* dr = det + ((size_t)b * MAXDET + s) * 6;
        dr[0] = d0; dr[1] = d1; dr[2] = d2; dr[3] = d3; dr[4] = d4; dr[5] = d5;
        vout[b * MAXDET + s] = v;
    }

    for (int e = tid; e < MAXDET * NCLS; e += 1024) {
        int s = e / NCLS, c = e % NCLS;
        float v = 0.0f;
        if (s < count) {
            int i   = sel[s];
            int idx = g_topk_idx[b * TOPK + i];
            v = logits[((size_t)b * NANCH + idx) * NCLS + c];
        }
        lout[((size_t)b * MAXDET + s) * NCLS + c] = v;
    }
}

// ---------------- launch --------------------------------------------------------
extern "C" void kernel_launch(void* const* d_in, const int* in_sizes, int n_in,
                              void* d_out, int out_size) {
    (void)in_sizes; (void)n_in; (void)out_size;
    const float* pred   = (const float*)d_in[0];
    const float* logits = (const float*)d_in[1];
    float* out = (float*)d_out;

    int total_warps = BATCH * NANCH;                 // one warp per anchor
    int blocks = (total_warps + 7) / 8;              // 256 threads = 8 warps per block
    k_score<<<blocks, 256>>>(pred);
    k_select<<<BATCH, 1024>>>(pred);
    k_mask<<<dim3(BATCH, 4), 1024>>>();
    k_out<<<BATCH, 1024>>>(pred, logits, out);
}

// round 3
// speedup vs baseline: 1.3437x; 1.3437x over previous
#include <cuda_runtime.h>
#include <cstdint>

#define BATCH   16
#define NANCH   25200
#define NCH     85
#define NCLS    80
#define TOPK    1024
#define MAXDET  300
#define CONF_THR 0.6f
#define IOU_THR  0.45f
#define OFFS     4096.0f
#define NBINS    4096
#define CHUNK    256          // mask rows staged per smem chunk in k_out

// ---------------- static device scratch (no allocations allowed) ----------------
__device__ float         g_score[BATCH * NANCH];
__device__ unsigned char g_cls[BATCH * NANCH];
__device__ int           g_topk_idx[BATCH * TOPK];
__device__ float         g_topk_score[BATCH * TOPK];
__device__ float4        g_nmsbox[BATCH * TOPK];
__device__ unsigned int  g_mask[BATCH * TOPK * 32];

// ---------------- K1: per-anchor score / class (warp per anchor) ----------------
__global__ void k_score(const float* __restrict__ pred) {
    int gwarp = (blockIdx.x * blockDim.x + threadIdx.x) >> 5;
    int lane  = threadIdx.x & 31;
    if (gwarp >= BATCH * NANCH) return;
    const float* base = pred + (size_t)gwarp * NCH;
    float obj = base[4];
    // products first (matches reference: cls_scores = pred[5:] * obj, then max/argmax)
    float best = -2.0f; int bidx = 0;
    #pragma unroll
    for (int r = 0; r < 3; r++) {
        int j = lane + 32 * r;
        if (j < NCLS) {
            float p = __fmul_rn(obj, base[5 + j]);
            if (p > best) { best = p; bidx = j; }   // strict > keeps lower index on tie
        }
    }
    #pragma unroll
    for (int off = 16; off > 0; off >>= 1) {
        float ob = __shfl_down_sync(0xffffffffu, best, off);
        int   oi = __shfl_down_sync(0xffffffffu, bidx, off);
        if (ob > best || (ob == best && oi < bidx)) { best = ob; bidx = oi; }
    }
    if (lane == 0) {
        bool valid = (obj > CONF_THR) && (best > CONF_THR);
        g_score[gwarp] = valid ? best : -1.0f;
        g_cls[gwarp]   = (unsigned char)bidx;
    }
}

// ---------------- K2: per-image exact top-1024 via histogram + bitonic sort -----
__global__ void k_select(const float* __restrict__ pred) {
    int b   = blockIdx.x;
    int tid = threadIdx.x;                 // 1024 threads
    __shared__ int hist[NBINS];
    __shared__ unsigned long long sbuf[2 * TOPK];
    __shared__ int partial[1024];
    __shared__ int sup[32];
    __shared__ int sh_T;
    __shared__ int counter;

    for (int i = tid; i < NBINS; i += 1024) hist[i] = 0;
    if (tid == 0) counter = 0;
    __syncthreads();

    const float* sc = g_score + (size_t)b * NANCH;
    const float kBinScale = (float)NBINS / 0.4f;

    for (int i = tid; i < NANCH; i += 1024) {
        float s = sc[i];
        if (s > CONF_THR) {
            int bin = (int)((s - CONF_THR) * kBinScale);
            bin = min(max(bin, 0), NBINS - 1);
            atomicAdd(&hist[bin], 1);
        }
    }
    __syncthreads();

    int ps = 0;
    #pragma unroll
    for (int k = 0; k < 4; k++) ps += hist[4 * tid + k];
    partial[tid] = ps;
    __syncthreads();

    if (tid < 32) {
        int s = 0;
        for (int g = 0; g < 32; g++) s += partial[32 * tid + g];
        sup[tid] = s;
        __syncwarp();
        if (tid == 0) {
            int acc = 0, T = 0, l;
            for (l = 31; l >= 0; l--) { if (acc + sup[l] >= TOPK) break; acc += sup[l]; }
            if (l >= 0) {
                int g;
                for (g = 31; g >= 0; g--) { int v = partial[32 * l + g]; if (acc + v >= TOPK) break; acc += v; }
                if (g < 0) g = 0;
                int bb;
                for (bb = 3; bb >= 0; bb--) { int v = hist[4 * (32 * l + g) + bb]; if (acc + v >= TOPK) break; acc += v; }
                if (bb < 0) bb = 0;
                T = 4 * (32 * l + g) + bb;
            }
            sh_T = T;
        }
    }
    __syncthreads();
    int T = sh_T;

    for (int i = tid; i < NANCH; i += 1024) {
        float s = sc[i];
        if (s > CONF_THR) {
            int bin = (int)((s - CONF_THR) * kBinScale);
            bin = min(max(bin, 0), NBINS - 1);
            if (bin >= T) {
                int pos = atomicAdd(&counter, 1);
                if (pos < 2 * TOPK) {
                    unsigned int u = __float_as_uint(s) ^ 0x80000000u;  // positive float -> order-preserving
                    sbuf[pos] = (((unsigned long long)(~u)) << 32) | (unsigned int)i;
                }
            }
        }
    }
    __syncthreads();
    int M = min(counter, 2 * TOPK);
    for (int i = tid; i < 2 * TOPK; i += 1024)
        if (i >= M) sbuf[i] = 0xFFFFFFFFFFFFFFFFull;
    __syncthreads();

    // bitonic sort ascending: primary ~score_bits (=> score descending), ties idx ascending
    for (int k = 2; k <= 2 * TOPK; k <<= 1) {
        for (int j = k >> 1; j > 0; j >>= 1) {
            for (int e = tid; e < 2 * TOPK; e += 1024) {
                int partner = e ^ j;
                if (partner > e) {
                    bool asc = ((e & k) == 0);
                    unsigned long long a = sbuf[e], c = sbuf[partner];
                    if ((a > c) == asc) { sbuf[e] = c; sbuf[partner] = a; }
                }
            }
            __syncthreads();
        }
    }

    // emit top-1024: idx, score, class-offset nms box
    if (tid < TOPK) {
        int slot = b * TOPK + tid;
        if (tid < M) {
            unsigned long long key = sbuf[tid];
            int idx = (int)(key & 0xFFFFFFFFu);
            unsigned int u = ~((unsigned int)(key >> 32));
            float s = __uint_as_float(u ^ 0x80000000u);
            g_topk_score[slot] = s;
            g_topk_idx[slot]   = idx;
            const float* p = pred + ((size_t)b * NANCH + idx) * NCH;
            float cx = p[0], cy = p[1], w = p[2], h = p[3];
            float hw = __fmul_rn(w, 0.5f), hh = __fmul_rn(h, 0.5f);
            float x1 = __fsub_rn(cx, hw), y1 = __fsub_rn(cy, hh);
            float x2 = __fadd_rn(cx, hw), y2 = __fadd_rn(cy, hh);
            float off = __fmul_rn((float)g_cls[(size_t)b * NANCH + idx], OFFS);
            g_nmsbox[slot] = make_float4(__fadd_rn(x1, off), __fadd_rn(y1, off),
                                         __fadd_rn(x2, off), __fadd_rn(y2, off));
        } else {
            g_topk_score[slot] = -1.0f;
            g_topk_idx[slot]   = 0;
            float far = -1.0e9f - (float)tid * 16.0f;   // inert: never kept, never suppresses
            g_nmsbox[slot] = make_float4(far, far, far + 1.0f, far + 1.0f);
        }
    }
}

// ---------------- K3: suppression bitmask, iou computed exactly per reference ---
__global__ void k_mask() {
    int b = blockIdx.x, q = blockIdx.y;     // q in [0,4): column quarter
    int i = threadIdx.x;                    // 1024 threads, one row each
    __shared__ float4 boxes[TOPK];
    for (int t = threadIdx.x; t < TOPK; t += 1024) boxes[t] = g_nmsbox[b * TOPK + t];
    __syncthreads();

    float4 bi = boxes[i];
    float area_i = __fmul_rn(__fsub_rn(bi.z, bi.x), __fsub_rn(bi.w, bi.y));
    int j0 = q * 256;
    #pragma unroll
    for (int w = 0; w < 8; w++) {
        unsigned int m = 0;
        #pragma unroll 4
        for (int t = 0; t < 32; t++) {
            int j = j0 + w * 32 + t;
            if (j > i) {
                float4 bj = boxes[j];
                float area_j = __fmul_rn(__fsub_rn(bj.z, bj.x), __fsub_rn(bj.w, bj.y));
                float ltx = fmaxf(bi.x, bj.x), lty = fmaxf(bi.y, bj.y);
                float rbx = fminf(bi.z, bj.z), rby = fminf(bi.w, bj.w);
                float wx = fmaxf(__fsub_rn(rbx, ltx), 0.0f);
                float wy = fmaxf(__fsub_rn(rby, lty), 0.0f);
                float inter = __fmul_rn(wx, wy);
                float denom = __fadd_rn(__fsub_rn(__fadd_rn(area_i, area_j), inter), 1e-9f);
                float iou = inter / denom;
                if (iou > IOU_THR) m |= (1u << t);
            }
        }
        g_mask[((size_t)b * TOPK + i) * 32 + q * 8 + w] = m;
    }
}

// ---------------- K4: smem-staged greedy walk (warp) + parallel output emit -----
__global__ void k_out(const float* __restrict__ pred,
                      const float* __restrict__ logits,
                      float* __restrict__ out) {
    int b   = blockIdx.x;
    int tid = threadIdx.x;                  // 1024 threads
    __shared__ float        s_score[TOPK];                  // 4 KB
    __shared__ unsigned int s_mask[CHUNK * 32];             // 32 KB staged mask rows
    __shared__ int sel[MAXDET];
    __shared__ int sh_count;
    __shared__ int sh_stop;

    // stage scores once (coalesced)
    if (tid < TOPK) s_score[tid] = g_topk_score[b * TOPK + tid];
    if (tid == 0) { sh_stop = 0; sh_count = 0; }

    const unsigned int* gmask = g_mask + (size_t)b * TOPK * 32;

    unsigned int removed = 0;   // lane L owns suppression bits for columns [32L, 32L+32)
    int count = 0;

    #pragma unroll 1
    for (int c = 0; c < TOPK / CHUNK; c++) {
        __syncthreads();                    // publishes sh_stop; prev walk done before overwrite
        int stop = sh_stop;
        if (!stop) {
            // stage mask rows [c*CHUNK, (c+1)*CHUNK)  -- 8 coalesced words per thread
            #pragma unroll
            for (int t = 0; t < (CHUNK * 32) / 1024; t++)
                s_mask[t * 1024 + tid] = gmask[(size_t)c * CHUNK * 32 + t * 1024 + tid];
        }
        __syncthreads();
        if (stop) continue;

        if (tid < 32) {
            // warp-serial greedy walk over this chunk; removed words live in lane regs
            for (int i = c * CHUNK; i < (c + 1) * CHUNK; i++) {
                float s = s_score[i];                        // smem broadcast
                if (s <= CONF_THR) { if (tid == 0) sh_stop = 1; break; }
                unsigned int rw = __shfl_sync(0xffffffffu, removed, i >> 5);
                if (!((rw >> (i & 31)) & 1u)) {
                    removed |= s_mask[(i & (CHUNK - 1)) * 32 + tid];
                    if (tid == 0) sel[count] = i;
                    count++;
                    if (count == MAXDET) { if (tid == 0) sh_stop = 1; break; }
                }
            }
            if (tid == 0) sh_count = count;
        }
    }
    __syncthreads();
    count = sh_count;

    float* det  = out;                                      // [B,300,6]
    float* vout = out + BATCH * MAXDET * 6;                 // [B,300]
    float* lout = vout + BATCH * MAXDET;                    // [B,300,80]

    for (int s = tid; s < MAXDET; s += 1024) {
        float d0 = 0, d1 = 0, d2 = 0, d3 = 0, d4 = 0, d5 = 0, v = 0;
        if (s < count) {
            int i   = sel[s];
            int idx = g_topk_idx[b * TOPK + i];
            const float* p = pred + ((size_t)b * NANCH + idx) * NCH;
            float cx = p[0], cy = p[1], w = p[2], h = p[3];
            float hw = __fmul_rn(w, 0.5f), hh = __fmul_rn(h, 0.5f);
            d0 = __fsub_rn(cx, hw); d1 = __fsub_rn(cy, hh);
            d2 = __fadd_rn(cx, hw); d3 = __fadd_rn(cy, hh);
            d4 = s_score[i];
            d5 = (float)g_cls[(size_t)b * NANCH + idx];
            v = 1.0f;
        }
        float* dr = det + ((size_t)b * MAXDET + s) * 6;
        dr[0] = d0; dr[1] = d1; dr[2] = d2; dr[3] = d3; dr[4] = d4; dr[5] = d5;
        vout[b * MAXDET + s] = v;
    }

    for (int e = tid; e < MAXDET * NCLS; e += 1024) {
        int s = e / NCLS, c = e % NCLS;
        float v = 0.0f;
        if (s < count) {
            int i   = sel[s];
            int idx = g_topk_idx[b * TOPK + i];
            v = logits[((size_t)b * NANCH + idx) * NCLS + c];
        }
        lout[((size_t)b * MAXDET + s) * NCLS + c] = v;
    }
}

// ---------------- launch --------------------------------------------------------
extern "C" void kernel_launch(void* const* d_in, const int* in_sizes, int n_in,
                              void* d_out, int out_size) {
    (void)in_sizes; (void)n_in; (void)out_size;
    const float* pred   = (const float*)d_in[0];
    const float* logits = (const float*)d_in[1];
    float* out = (float*)d_out;

    int total_warps = BATCH * NANCH;                 // one warp per anchor
    int blocks = (total_warps + 7) / 8;              // 256 threads = 8 warps per block
    k_score<<<blocks, 256>>>(pred);
    k_select<<<BATCH, 1024>>>(pred);
    k_mask<<<dim3(BATCH, 4), 1024>>>();
    k_out<<<BATCH, 1024>>>(pred, logits, out);
}